// round 13
// baseline (speedup 1.0000x reference)
#include <cuda_runtime.h>
#include <cuda_bf16.h>
#include <cstdint>
#include <math.h>

#define NB   8192
#define DK   512
#define NCAP 256
#define INV_T 14.285714285714285f
#define NTILES 2080            // 64*65/2 upper-triangle 128x128 tiles
#define NCTA   2072            // 296 slots x 7 exact waves
#define EXTRA  (NTILES - NCTA) // first EXTRA CTAs run 2 tiles

// ---------------- device scratch ----------------
__device__ float g_S[NB];
__device__ int   g_cnt[NB];
__device__ float g_scr[NB * NCAP];
__device__ float g_partial[64];
__device__ unsigned g_ticket;
__device__ __nv_bfloat16 g_bf[NB * DK];

// ---------------- tile geometry: CTA 128x128 (512 thr), warp 32x32, BK=64, 2 stages ----
#define TSTR    72                     // halves per smem row (144B)
#define TILE_B  (128 * TSTR * 2)       // 18432 per 128x64 bf16 tile
#define STAGE_B (2 * TILE_B)           // A+B per stage = 36864
#define SM_LAB  (2 * STAGE_B)          // 73728
#define SM_TOTAL (SM_LAB + 1024)

// ---------------- helpers ----------------
__device__ __forceinline__ uint32_t smem_u32(const void* p) {
    uint32_t a;
    asm("{ .reg .u64 t; cvta.to.shared.u64 t, %1; cvt.u32.u64 %0, t; }" : "=r"(a) : "l"(p));
    return a;
}
__device__ __forceinline__ void cp16(uint32_t dst, const void* src) {
    asm volatile("cp.async.cg.shared.global [%0], [%1], 16;" :: "r"(dst), "l"(src));
}
__device__ __forceinline__ void cp_commit() { asm volatile("cp.async.commit_group;"); }
template<int N> __device__ __forceinline__ void cp_wait() {
    asm volatile("cp.async.wait_group %0;" :: "n"(N));
}
__device__ __forceinline__ void ldsm4(uint32_t& r0, uint32_t& r1, uint32_t& r2, uint32_t& r3,
                                      uint32_t addr) {
    asm volatile("ldmatrix.sync.aligned.m8n8.x4.shared.b16 {%0,%1,%2,%3}, [%4];"
                 : "=r"(r0), "=r"(r1), "=r"(r2), "=r"(r3) : "r"(addr));
}
__device__ __forceinline__ void mma16816(float* c, const uint32_t* a, const uint32_t* b) {
    asm volatile("mma.sync.aligned.m16n8k16.row.col.f32.bf16.bf16.f32 "
                 "{%0,%1,%2,%3},{%4,%5,%6,%7},{%8,%9},{%0,%1,%2,%3};"
                 : "+f"(c[0]), "+f"(c[1]), "+f"(c[2]), "+f"(c[3])
                 : "r"(a[0]), "r"(a[1]), "r"(a[2]), "r"(a[3]), "r"(b[0]), "r"(b[1]));
}

// fp32 -> bf16 (8 elems/thread) + zero accumulators
__global__ void convert_kernel(const float* __restrict__ E) {
    int i = blockIdx.x * blockDim.x + threadIdx.x;
    if (i < NB) { g_S[i] = 0.f; g_cnt[i] = 0; }
    const float4* p = (const float4*)E + (size_t)i * 2;
    float4 x = p[0], y = p[1];
    __nv_bfloat162 h0 = __floats2bfloat162_rn(x.x, x.y);
    __nv_bfloat162 h1 = __floats2bfloat162_rn(x.z, x.w);
    __nv_bfloat162 h2 = __floats2bfloat162_rn(y.x, y.y);
    __nv_bfloat162 h3 = __floats2bfloat162_rn(y.z, y.w);
    uint4 o;
    o.x = *(uint32_t*)&h0; o.y = *(uint32_t*)&h1;
    o.z = *(uint32_t*)&h2; o.w = *(uint32_t*)&h3;
    *((uint4*)g_bf + (size_t)i) = o;
}

extern __shared__ char smem[];

// Upper-triangle 128x128-tiled symmetric GEMM (E E^T), 512 threads, warp 32x32,
// single barrier per k-chunk, fused SINCERE epilogue. Tail-balanced: first EXTRA
// CTAs process a second tile (b + NCTA).
__global__ void __launch_bounds__(512, 2) gemm_mma(const int* __restrict__ lab) {
    const int t   = threadIdx.x;
    const int lid = t & 31;
    const int wid = t >> 5;          // 0..15
    const int warp_m = wid & 3;      // 4 warps down  (32 rows each)
    const int warp_n = wid >> 2;     // 4 warps across (32 cols each)

    uint32_t sb = smem_u32(smem);
    int* sLI = (int*)(smem + SM_LAB);
    int* sLJ = sLI + 128;
    const int r_l4 = lid >> 2, c_l4 = lid & 3;
    const int nrep = (blockIdx.x < EXTRA) ? 2 : 1;

    for (int rep = 0; rep < nrep; rep++) {
        int b = blockIdx.x + rep * NCTA;

        // decode upper-triangle tile (ti <= tj)
        int ti = (int)((129.0 - sqrt(129.0 * 129.0 - 8.0 * (double)b)) * 0.5);
        while (ti * (129 - ti) / 2 > b) ti--;
        while ((ti + 1) * (128 - ti) / 2 <= b) ti++;
        const int tj = ti + (b - ti * (129 - ti) / 2);
        const int i0 = ti * 128, j0 = tj * 128;

        if (rep) __syncthreads();    // prior epilogue label reads done before rewrite
        if (t < 128)        sLI[t] = lab[i0 + t];
        else if (t < 256)   sLJ[t - 128] = lab[j0 + (t - 128)];

        float acc[2][4][4];
#pragma unroll
        for (int mi = 0; mi < 2; mi++)
#pragma unroll
            for (int ni = 0; ni < 4; ni++)
#pragma unroll
                for (int r = 0; r < 4; r++) acc[mi][ni][r] = 0.f;

        const __nv_bfloat16* srcA = g_bf + (size_t)i0 * DK;
        const __nv_bfloat16* srcB = g_bf + (size_t)j0 * DK;

        auto load_chunk = [&](int s, int kc) {
            uint32_t soA = sb + s * STAGE_B;
            uint32_t soB = soA + TILE_B;
#pragma unroll
            for (int i = 0; i < 2; i++) {
                int v = t + i * 512;
                int row = v >> 3, q = v & 7;
                cp16(soA + row * (TSTR * 2) + q * 16, srcA + (size_t)row * DK + kc * 64 + q * 8);
                cp16(soB + row * (TSTR * 2) + q * 16, srcB + (size_t)row * DK + kc * 64 + q * 8);
            }
        };

        load_chunk(0, 0); cp_commit();

#pragma unroll 1
        for (int kc = 0; kc < 8; kc++) {
            int s = kc & 1;
            cp_wait<0>();
            __syncthreads();
            if (kc < 7) { load_chunk(s ^ 1, kc + 1); cp_commit(); }

            const uint32_t aT = sb + s * STAGE_B;
            const uint32_t bT = aT + TILE_B;

#pragma unroll
            for (int ks = 0; ks < 4; ks++) {
                const uint32_t a_off =
                    (warp_m * 32 + (lid & 15)) * (TSTR * 2) + (ks * 16 + (lid >> 4) * 8) * 2;
                const uint32_t b_off =
                    (warp_n * 32 + (lid & 7) + ((lid & 16) ? 8 : 0)) * (TSTR * 2) +
                    (ks * 16 + ((lid >> 3) & 1) * 8) * 2;

                uint32_t a[2][4], bb[4][2];
                ldsm4(a[0][0], a[0][1], a[0][2], a[0][3], aT + a_off);
                ldsm4(a[1][0], a[1][1], a[1][2], a[1][3], aT + a_off + 16 * (TSTR * 2));
#pragma unroll
                for (int np = 0; np < 2; np++)
                    ldsm4(bb[2 * np][0], bb[2 * np][1], bb[2 * np + 1][0], bb[2 * np + 1][1],
                          bT + b_off + np * 16 * (TSTR * 2));
#pragma unroll
                for (int mi = 0; mi < 2; mi++)
#pragma unroll
                    for (int ni = 0; ni < 4; ni++) mma16816(acc[mi][ni], a[mi], bb[ni]);
            }
        }

        // ---------------- fused epilogue ----------------
        float rowacc[2][2] = {{0.f, 0.f}, {0.f, 0.f}};
        float colacc[4][2];
#pragma unroll
        for (int ni = 0; ni < 4; ni++) { colacc[ni][0] = 0.f; colacc[ni][1] = 0.f; }

#pragma unroll
        for (int mi = 0; mi < 2; mi++)
#pragma unroll
            for (int ni = 0; ni < 4; ni++)
#pragma unroll
                for (int r = 0; r < 4; r++) {
                    int irow = warp_m * 32 + mi * 16 + (r >> 1) * 8 + r_l4;
                    int jcol = warp_n * 32 + ni * 8 + c_l4 * 2 + (r & 1);
                    int gi = i0 + irow, gj = j0 + jcol;
                    if (gj > gi) {
                        float L = acc[mi][ni][r] * INV_T;
                        if (sLI[irow] != sLJ[jcol]) {
                            float e = __expf(L - INV_T);
                            rowacc[mi][r >> 1] += e;
                            colacc[ni][r & 1] += e;
                        } else {
                            int p = atomicAdd(&g_cnt[gi], 1);
                            if (p < NCAP) g_scr[gi * NCAP + p] = L;
                            int q = atomicAdd(&g_cnt[gj], 1);
                            if (q < NCAP) g_scr[gj * NCAP + q] = L;
                        }
                    }
                }

#pragma unroll
        for (int mi = 0; mi < 2; mi++)
#pragma unroll
            for (int rp = 0; rp < 2; rp++) {
                float v = rowacc[mi][rp];
                v += __shfl_xor_sync(0xffffffffu, v, 1);
                v += __shfl_xor_sync(0xffffffffu, v, 2);
                if (c_l4 == 0 && v != 0.f)
                    atomicAdd(&g_S[i0 + warp_m * 32 + mi * 16 + rp * 8 + r_l4], v);
            }
#pragma unroll
        for (int ni = 0; ni < 4; ni++)
#pragma unroll
            for (int c = 0; c < 2; c++) {
                float v = colacc[ni][c];
                v += __shfl_xor_sync(0xffffffffu, v, 4);
                v += __shfl_xor_sync(0xffffffffu, v, 8);
                v += __shfl_xor_sync(0xffffffffu, v, 16);
                if (r_l4 == 0 && v != 0.f)
                    atomicAdd(&g_S[j0 + warp_n * 32 + ni * 8 + c_l4 * 2 + c], v);
            }
    }
}

// Fused pass 2 + deterministic final reduce
__global__ void rowloss_reduce_kernel(float* __restrict__ out) {
    const int lid = threadIdx.x & 31;
    const int wIn = threadIdx.x >> 5;
    const int wG  = blockIdx.x * 8 + wIn;
    float wsum = 0.f;
    for (int i = wG; i < NB; i += 512) {
        int c = g_cnt[i];
        if (c > 0) {
            float base = logf(g_S[i]) + INV_T;
            float s = 0.f;
            int cap = c < NCAP ? c : NCAP;
            for (int p = lid; p < cap; p += 32)
                s += log1pf(__expf(base - g_scr[i * NCAP + p]));
            s += __shfl_xor_sync(0xffffffffu, s, 16);
            s += __shfl_xor_sync(0xffffffffu, s, 8);
            s += __shfl_xor_sync(0xffffffffu, s, 4);
            s += __shfl_xor_sync(0xffffffffu, s, 2);
            s += __shfl_xor_sync(0xffffffffu, s, 1);
            wsum += s / (float)c;
        }
    }
    __shared__ float sw[8];
    if (lid == 0) sw[wIn] = wsum;
    __syncthreads();
    if (threadIdx.x == 0) {
        float bs = 0.f;
#pragma unroll
        for (int w = 0; w < 8; w++) bs += sw[w];
        g_partial[blockIdx.x] = bs;
        __threadfence();
        unsigned tk = atomicInc(&g_ticket, 63u);
        if (tk == 63u) {
            float tot = 0.f;
            for (int k = 0; k < 64; k++) tot += g_partial[k];
            out[0] = tot * (1.0f / (float)NB);
        }
    }
}

extern "C" void kernel_launch(void* const* d_in, const int* in_sizes, int n_in,
                              void* d_out, int out_size) {
    const float* E   = (const float*)d_in[0];
    const int*   lab = (const int*)d_in[1];
    float*       out = (float*)d_out;

    static bool attr_set = false;
    if (!attr_set) {
        cudaFuncSetAttribute(gemm_mma, cudaFuncAttributeMaxDynamicSharedMemorySize, SM_TOTAL);
        attr_set = true;
    }

    convert_kernel<<<(NB * DK) / 8 / 256, 256>>>(E);
    gemm_mma<<<NCTA, 512, SM_TOTAL>>>(lab);
    rowloss_reduce_kernel<<<64, 256>>>(out);
}

// round 14
// speedup vs baseline: 1.0835x; 1.0835x over previous
#include <cuda_runtime.h>
#include <cuda_bf16.h>
#include <cstdint>
#include <math.h>

#define NB   8192
#define DK   512
#define NCAP 256
#define INV_T 14.285714285714285f
#define NTILES 4160            // sum over ti of (128-2*ti), 128x64 tiles, tj>=2*ti

// ---------------- device scratch ----------------
__device__ float g_S[NB];
__device__ int   g_cnt[NB];
__device__ float g_scr[NB * NCAP];
__device__ float g_partial[128];
__device__ unsigned g_ticket;
__device__ __nv_bfloat16 g_bf[NB * DK];

// ---------------- tile geometry: CTA 128x64, warp 32x32, BK=64, 2 stages ----------------
#define TSTR     72                    // halves per smem row (144B)
#define A_TILE_B (128 * TSTR * 2)      // 18432
#define B_TILE_B (64 * TSTR * 2)       // 9216
#define STAGE_B  (A_TILE_B + B_TILE_B) // 27648
#define SM_LAB   (2 * STAGE_B)         // 55296
#define SM_TOTAL (SM_LAB + 1024)

// ---------------- helpers ----------------
__device__ __forceinline__ uint32_t smem_u32(const void* p) {
    uint32_t a;
    asm("{ .reg .u64 t; cvta.to.shared.u64 t, %1; cvt.u32.u64 %0, t; }" : "=r"(a) : "l"(p));
    return a;
}
__device__ __forceinline__ void cp16(uint32_t dst, const void* src) {
    asm volatile("cp.async.cg.shared.global [%0], [%1], 16;" :: "r"(dst), "l"(src));
}
__device__ __forceinline__ void cp_commit() { asm volatile("cp.async.commit_group;"); }
template<int N> __device__ __forceinline__ void cp_wait() {
    asm volatile("cp.async.wait_group %0;" :: "n"(N));
}
__device__ __forceinline__ void ldsm4(uint32_t& r0, uint32_t& r1, uint32_t& r2, uint32_t& r3,
                                      uint32_t addr) {
    asm volatile("ldmatrix.sync.aligned.m8n8.x4.shared.b16 {%0,%1,%2,%3}, [%4];"
                 : "=r"(r0), "=r"(r1), "=r"(r2), "=r"(r3) : "r"(addr));
}
__device__ __forceinline__ void mma16816(float* c, const uint32_t* a, const uint32_t* b) {
    asm volatile("mma.sync.aligned.m16n8k16.row.col.f32.bf16.bf16.f32 "
                 "{%0,%1,%2,%3},{%4,%5,%6,%7},{%8,%9},{%0,%1,%2,%3};"
                 : "+f"(c[0]), "+f"(c[1]), "+f"(c[2]), "+f"(c[3])
                 : "r"(a[0]), "r"(a[1]), "r"(a[2]), "r"(a[3]), "r"(b[0]), "r"(b[1]));
}

// fp32 -> bf16 (8 elems/thread) + zero accumulators
__global__ void convert_kernel(const float* __restrict__ E) {
    int i = blockIdx.x * blockDim.x + threadIdx.x;
    if (i < NB) { g_S[i] = 0.f; g_cnt[i] = 0; }
    const float4* p = (const float4*)E + (size_t)i * 2;
    float4 x = p[0], y = p[1];
    __nv_bfloat162 h0 = __floats2bfloat162_rn(x.x, x.y);
    __nv_bfloat162 h1 = __floats2bfloat162_rn(x.z, x.w);
    __nv_bfloat162 h2 = __floats2bfloat162_rn(y.x, y.y);
    __nv_bfloat162 h3 = __floats2bfloat162_rn(y.z, y.w);
    uint4 o;
    o.x = *(uint32_t*)&h0; o.y = *(uint32_t*)&h1;
    o.z = *(uint32_t*)&h2; o.w = *(uint32_t*)&h3;
    *((uint4*)g_bf + (size_t)i) = o;
}

extern __shared__ char smem[];

// Upper-triangle 128x64-tiled symmetric GEMM (E E^T) on bf16 HMMA, 2-stage pipeline,
// fused SINCERE epilogue; each valid (gj>gi) element feeds row gi AND col gj.
// (R11-proven configuration: 4 CTAs/SM, 64 regs.)
__global__ void __launch_bounds__(256, 4) gemm_mma(const int* __restrict__ lab) {
    const int t   = threadIdx.x;
    const int lid = t & 31;
    const int wid = t >> 5;
    const int warp_m = wid & 3;     // 4 warps down  (32 rows each)
    const int warp_n = wid >> 2;    // 2 warps across (32 cols each)

    // decode tile: cum(ti) = ti*(129-ti); tj = 2*ti + rem (64-col units)
    int b  = blockIdx.x;
    int ti = (int)((129.0 - sqrt(129.0 * 129.0 - 4.0 * (double)b)) * 0.5);
    while (ti * (129 - ti) > b) ti--;
    while ((ti + 1) * (128 - ti) <= b) ti++;
    const int tj = 2 * ti + (b - ti * (129 - ti));
    const int i0 = ti * 128, j0 = tj * 64;

    uint32_t sb = smem_u32(smem);
    int* sLI = (int*)(smem + SM_LAB);    // 128
    int* sLJ = sLI + 128;                // 64
    if (t < 128)            sLI[t] = lab[i0 + t];
    else if (t < 192)       sLJ[t - 128] = lab[j0 + (t - 128)];

    float acc[2][4][4];
#pragma unroll
    for (int mi = 0; mi < 2; mi++)
#pragma unroll
        for (int ni = 0; ni < 4; ni++)
#pragma unroll
            for (int r = 0; r < 4; r++) acc[mi][ni][r] = 0.f;

    const __nv_bfloat16* srcA = g_bf + (size_t)i0 * DK;
    const __nv_bfloat16* srcB = g_bf + (size_t)j0 * DK;

    auto load_chunk = [&](int s, int kc) {
        uint32_t soA = sb + s * STAGE_B;
        uint32_t soB = soA + A_TILE_B;
#pragma unroll
        for (int i = 0; i < 4; i++) {        // A: 128x64 bf16 = 1024 uint4
            int v = t + i * 256;
            int row = v >> 3, q = v & 7;
            cp16(soA + row * (TSTR * 2) + q * 16,
                 srcA + (size_t)row * DK + kc * 64 + q * 8);
        }
#pragma unroll
        for (int i = 0; i < 2; i++) {        // B: 64x64 bf16 = 512 uint4
            int v = t + i * 256;
            int row = v >> 3, q = v & 7;
            cp16(soB + row * (TSTR * 2) + q * 16,
                 srcB + (size_t)row * DK + kc * 64 + q * 8);
        }
    };

    load_chunk(0, 0); cp_commit();

#pragma unroll 1
    for (int kc = 0; kc < 8; kc++) {
        int s = kc & 1;
        if (kc < 7) { load_chunk(s ^ 1, kc + 1); cp_commit(); cp_wait<1>(); }
        else        { cp_wait<0>(); }
        __syncthreads();

        const uint32_t aT = sb + s * STAGE_B;
        const uint32_t bT = aT + A_TILE_B;

#pragma unroll
        for (int ks = 0; ks < 4; ks++) {
            const uint32_t a_off =
                (warp_m * 32 + (lid & 15)) * (TSTR * 2) + (ks * 16 + (lid >> 4) * 8) * 2;
            const uint32_t b_off =
                (warp_n * 32 + (lid & 7) + ((lid & 16) ? 8 : 0)) * (TSTR * 2) +
                (ks * 16 + ((lid >> 3) & 1) * 8) * 2;

            uint32_t a[2][4], bb[4][2];
            ldsm4(a[0][0], a[0][1], a[0][2], a[0][3], aT + a_off);
            ldsm4(a[1][0], a[1][1], a[1][2], a[1][3], aT + a_off + 16 * (TSTR * 2));
#pragma unroll
            for (int np = 0; np < 2; np++)
                ldsm4(bb[2 * np][0], bb[2 * np][1], bb[2 * np + 1][0], bb[2 * np + 1][1],
                      bT + b_off + np * 16 * (TSTR * 2));
#pragma unroll
            for (int mi = 0; mi < 2; mi++)
#pragma unroll
                for (int ni = 0; ni < 4; ni++) mma16816(acc[mi][ni], a[mi], bb[ni]);
        }
        __syncthreads();
    }

    // ---------------- fused epilogue ----------------
    const int r_l4 = lid >> 2, c_l4 = lid & 3;
    float rowacc[2][2] = {{0.f, 0.f}, {0.f, 0.f}};
    float colacc[4][2];
#pragma unroll
    for (int ni = 0; ni < 4; ni++) { colacc[ni][0] = 0.f; colacc[ni][1] = 0.f; }

#pragma unroll
    for (int mi = 0; mi < 2; mi++)
#pragma unroll
        for (int ni = 0; ni < 4; ni++)
#pragma unroll
            for (int r = 0; r < 4; r++) {
                int irow = warp_m * 32 + mi * 16 + (r >> 1) * 8 + r_l4;
                int jcol = warp_n * 32 + ni * 8 + c_l4 * 2 + (r & 1);
                int gi = i0 + irow, gj = j0 + jcol;
                if (gj > gi) {
                    float L = acc[mi][ni][r] * INV_T;
                    if (sLI[irow] != sLJ[jcol]) {
                        float e = __expf(L - INV_T);
                        rowacc[mi][r >> 1] += e;
                        colacc[ni][r & 1] += e;
                    } else {
                        int p = atomicAdd(&g_cnt[gi], 1);
                        if (p < NCAP) g_scr[gi * NCAP + p] = L;
                        int q = atomicAdd(&g_cnt[gj], 1);
                        if (q < NCAP) g_scr[gj * NCAP + q] = L;
                    }
                }
            }

#pragma unroll
    for (int mi = 0; mi < 2; mi++)
#pragma unroll
        for (int rp = 0; rp < 2; rp++) {
            float v = rowacc[mi][rp];
            v += __shfl_xor_sync(0xffffffffu, v, 1);
            v += __shfl_xor_sync(0xffffffffu, v, 2);
            if (c_l4 == 0 && v != 0.f)
                atomicAdd(&g_S[i0 + warp_m * 32 + mi * 16 + rp * 8 + r_l4], v);
        }
#pragma unroll
    for (int ni = 0; ni < 4; ni++)
#pragma unroll
        for (int c = 0; c < 2; c++) {
            float v = colacc[ni][c];
            v += __shfl_xor_sync(0xffffffffu, v, 4);
            v += __shfl_xor_sync(0xffffffffu, v, 8);
            v += __shfl_xor_sync(0xffffffffu, v, 16);
            if (r_l4 == 0 && v != 0.f)
                atomicAdd(&g_S[j0 + warp_n * 32 + ni * 8 + c_l4 * 2 + c], v);
        }
}

// Fused pass 2 + deterministic final reduce (128 blocks)
__global__ void rowloss_reduce_kernel(float* __restrict__ out) {
    const int lid = threadIdx.x & 31;
    const int wIn = threadIdx.x >> 5;
    const int wG  = blockIdx.x * 8 + wIn;            // 1024 warps
    float wsum = 0.f;
    for (int i = wG; i < NB; i += 1024) {
        int c = g_cnt[i];
        if (c > 0) {
            float base = logf(g_S[i]) + INV_T;
            float s = 0.f;
            int cap = c < NCAP ? c : NCAP;
            for (int p = lid; p < cap; p += 32)
                s += log1pf(__expf(base - g_scr[i * NCAP + p]));
            s += __shfl_xor_sync(0xffffffffu, s, 16);
            s += __shfl_xor_sync(0xffffffffu, s, 8);
            s += __shfl_xor_sync(0xffffffffu, s, 4);
            s += __shfl_xor_sync(0xffffffffu, s, 2);
            s += __shfl_xor_sync(0xffffffffu, s, 1);
            wsum += s / (float)c;
        }
    }
    __shared__ float sw[8];
    if (lid == 0) sw[wIn] = wsum;
    __syncthreads();
    if (threadIdx.x == 0) {
        float bs = 0.f;
#pragma unroll
        for (int w = 0; w < 8; w++) bs += sw[w];
        g_partial[blockIdx.x] = bs;
        __threadfence();
        unsigned tk = atomicInc(&g_ticket, 127u);    // wraps to 0 after 128th
        if (tk == 127u) {
            float tot = 0.f;
            for (int k = 0; k < 128; k++) tot += g_partial[k];
            out[0] = tot * (1.0f / (float)NB);
        }
    }
}

extern "C" void kernel_launch(void* const* d_in, const int* in_sizes, int n_in,
                              void* d_out, int out_size) {
    const float* E   = (const float*)d_in[0];
    const int*   lab = (const int*)d_in[1];
    float*       out = (float*)d_out;

    static bool attr_set = false;
    if (!attr_set) {
        cudaFuncSetAttribute(gemm_mma, cudaFuncAttributeMaxDynamicSharedMemorySize, SM_TOTAL);
        attr_set = true;
    }

    convert_kernel<<<(NB * DK) / 8 / 256, 256>>>(E);
    gemm_mma<<<NTILES, 256, SM_TOTAL>>>(lab);
    rowloss_reduce_kernel<<<128, 256>>>(out);
}